// round 16
// baseline (speedup 1.0000x reference)
#include <cuda_runtime.h>
#include <cuda_fp16.h>
#include <cstdint>

// ---------------------------------------------------------------------------
// Problem dims
// ---------------------------------------------------------------------------
#define HW        128
#define OW        126
#define LIN       15876              // (128-2)^2
#define K_TILE    64
#define N_KTILES  252                // LIN_PAD = 16128
#define LIN_PAD   (N_KTILES * K_TILE)
#define TRI       8256
#define BATCH     64
#define NDIM      128
#define T_PAD     8320               // 65*128
#define N_MTILES  65
#define NCTA      152                // GB300: 152 SMs, 1 CTA/SM
#define TOTAL_UNITS (N_MTILES * N_KTILES)   // 16380
#define NSLOTS    4

// SMEM layout, pitch 144 B (conflict-free ldmatrix).
// A: 3 stages x 18432 (fp16 128x64);  B: 3 stages x 9216 (fp16 64x64)
#define A_PITCH   144
#define A_STG     18432u
#define A_OFF(s)  ((uint32_t)(s) * A_STG)
#define B_BASE    55296u
#define B_STG     9216u
#define B_OFF(st) (B_BASE + (uint32_t)(st) * B_STG)
#define SMEM_BYTES 82944

// ---------------------------------------------------------------------------
// Scratch (device globals — no allocation allowed)
// ---------------------------------------------------------------------------
__device__ __half g_hb[(size_t)BATCH * LIN_PAD];   // [b][l] fp16 h
__device__ float  g_vp[(size_t)NSLOTS * BATCH * T_PAD];

// ---------------------------------------------------------------------------
// helpers
// ---------------------------------------------------------------------------
__device__ __forceinline__ uint32_t smem_u32(const void* p) {
    uint32_t a;
    asm("{ .reg .u64 t; cvta.to.shared.u64 t, %1; cvt.u32.u64 %0, t; }"
        : "=r"(a) : "l"(p));
    return a;
}

__device__ __forceinline__ void cp_async16(uint32_t dst, const void* src) {
    asm volatile("cp.async.cg.shared.global [%0], [%1], 16;"
                 :: "r"(dst), "l"(src) : "memory");
}
__device__ __forceinline__ void cp_commit() {
    asm volatile("cp.async.commit_group;" ::: "memory");
}
template <int N>
__device__ __forceinline__ void cp_wait() {
    asm volatile("cp.async.wait_group %0;" :: "n"(N) : "memory");
}

__device__ __forceinline__ void ldsm4(uint32_t* r, uint32_t addr) {
    asm volatile("ldmatrix.sync.aligned.m8n8.x4.shared.b16 {%0,%1,%2,%3}, [%4];"
                 : "=r"(r[0]), "=r"(r[1]), "=r"(r[2]), "=r"(r[3]) : "r"(addr));
}

__device__ __forceinline__ void mma_f16(float* c,
                                        uint32_t a0, uint32_t a1, uint32_t a2, uint32_t a3,
                                        uint32_t b0, uint32_t b1) {
    asm volatile(
        "mma.sync.aligned.m16n8k16.row.col.f32.f16.f16.f32 "
        "{%0,%1,%2,%3}, {%4,%5,%6,%7}, {%8,%9}, {%0,%1,%2,%3};"
        : "+f"(c[0]), "+f"(c[1]), "+f"(c[2]), "+f"(c[3])
        : "r"(a0), "r"(a1), "r"(a2), "r"(a3), "r"(b0), "r"(b1));
}

__device__ __forceinline__ uint32_t pack_h2(float x, float y) {
    __half2 h = __floats2half2_rn(x, y);
    return *reinterpret_cast<uint32_t*>(&h);
}

// unit-space partition: CTA j owns units [start_u(j), start_u(j+1))
__device__ __forceinline__ int start_u(int j) {
    return (int)(((long long)j * TOTAL_UNITS) / NCTA);
}

// ---------------------------------------------------------------------------
// Kernel 1: fused conv -> fp16 h, [b][l] layout (pad region zero)
// ---------------------------------------------------------------------------
__global__ void conv_fuse_kernel(const float* __restrict__ x,
                                 const float* __restrict__ w1,
                                 const float* __restrict__ b1,
                                 const float* __restrict__ w2,
                                 const float* __restrict__ b2) {
    int idx = blockIdx.x * blockDim.x + threadIdx.x;
    int b = idx / LIN_PAD;
    int l = idx - b * LIN_PAD;

    float val = 0.0f;
    if (l < LIN) {
        int i = l / OW;
        int j = l - i * OW;
        const float* xp = x + (size_t)b * (HW * HW) + i * HW + j;
        float acc = b2[0];
        #pragma unroll
        for (int c = 0; c < 4; c++) {
            float s = b1[c];
            #pragma unroll
            for (int di = 0; di < 3; di++)
                #pragma unroll
                for (int dj = 0; dj < 3; dj++)
                    s = fmaf(xp[di * HW + dj], w1[c * 9 + di * 3 + dj], s);
            acc = fmaf(w2[c], fmaxf(s, 0.0f), acc);
        }
        val = acc;
    }
    g_hb[idx] = __float2half(val);
}

// ---------------------------------------------------------------------------
// GEMM helpers (512 threads: arow = tid>>2, aq = tid&3)
// ---------------------------------------------------------------------------
__device__ __forceinline__ void ldg_a(const float* __restrict__ W,
                                      int t, int l0, int aq, bool trow_ok,
                                      float4 (&a)[4]) {
    #pragma unroll
    for (int j = 0; j < 4; j++) {
        int l = l0 + (aq * 4 + j) * 4;
        if (trow_ok && l < LIN)
            a[j] = *reinterpret_cast<const float4*>(W + (size_t)t * LIN + l);
        else
            a[j] = make_float4(0.f, 0.f, 0.f, 0.f);
    }
}

__device__ __forceinline__ void sts_a(char* smem, int stage, int row, int aq,
                                      const float4 (&a)[4]) {
    uint32_t base = A_OFF(stage) + (uint32_t)row * A_PITCH + (uint32_t)aq * 32;
    *reinterpret_cast<uint4*>(smem + base) =
        make_uint4(pack_h2(a[0].x, a[0].y), pack_h2(a[0].z, a[0].w),
                   pack_h2(a[1].x, a[1].y), pack_h2(a[1].z, a[1].w));
    *reinterpret_cast<uint4*>(smem + base + 16) =
        make_uint4(pack_h2(a[2].x, a[2].y), pack_h2(a[2].z, a[2].w),
                   pack_h2(a[3].x, a[3].y), pack_h2(a[3].z, a[3].w));
}

// B tile: 64 rows x 128 B = 512 chunks, one cp.async per thread
__device__ __forceinline__ void cpasync_b(uint32_t sb, int st, int ktg, int tid) {
    int row = tid >> 3;
    int ch  = tid & 7;
    uint32_t dst = sb + B_OFF(st) + (uint32_t)row * A_PITCH + (uint32_t)ch * 16;
    cp_async16(dst, g_hb + (size_t)row * LIN_PAD + ktg * K_TILE + ch * 8);
}

// warp tile 32(m) x 16(n): 4 ksteps, fragment double-buffer (prefetch +1)
__device__ __forceinline__ void compute_tile(uint32_t sb, int stage, int bst,
                                             int wm, int wn, int lid,
                                             float (&acc)[2][2][4]) {
    const uint32_t lrow = (uint32_t)(lid & 15);
    const uint32_t lhi  = (uint32_t)((lid >> 4) << 4);

    uint32_t aH0 = sb + A_OFF(stage) + (wm * 32 + lrow) * A_PITCH + lhi;
    uint32_t aH1 = aH0 + 16 * A_PITCH;
    uint32_t bH  = sb + B_OFF(bst) + (wn * 16 + lrow) * A_PITCH + lhi;

    uint32_t a0[2][4], a1[2][4], bb[2][4];
    ldsm4(a0[0], aH0);
    ldsm4(a1[0], aH1);
    ldsm4(bb[0], bH);

    #pragma unroll
    for (int ks = 0; ks < 4; ks++) {
        const int cur = ks & 1;
        const int nxt = cur ^ 1;
        if (ks < 3) {
            const uint32_t ko = (uint32_t)(ks + 1) * 32;
            ldsm4(a0[nxt], aH0 + ko);
            ldsm4(a1[nxt], aH1 + ko);
            ldsm4(bb[nxt], bH + ko);
        }
        mma_f16(acc[0][0], a0[cur][0], a0[cur][1], a0[cur][2], a0[cur][3],
                bb[cur][0], bb[cur][2]);
        mma_f16(acc[0][1], a0[cur][0], a0[cur][1], a0[cur][2], a0[cur][3],
                bb[cur][1], bb[cur][3]);
        mma_f16(acc[1][0], a1[cur][0], a1[cur][1], a1[cur][2], a1[cur][3],
                bb[cur][0], bb[cur][2]);
        mma_f16(acc[1][1], a1[cur][0], a1[cur][1], a1[cur][2], a1[cur][3],
                bb[cur][1], bb[cur][3]);
    }
}

__device__ __forceinline__ int mod3(int k) {
    // k small positive
    int r = k;
    while (r >= 3) r -= 3;
    return r;
}

// one pipelined segment: M-tile `mtile`, K-tiles [kt0, kt0+n_kt) -> slot
// A: 3 smem stages, 2 reg staging buffers, LDG 3 tiles ahead.
// Prefetch K-tile indices are clamped to N_KTILES-1 (in-bounds, unused data).
__device__ __forceinline__ void gemm_segment(const float* __restrict__ W,
                                             char* smem, uint32_t sb,
                                             int mtile, int kt0, int n_kt,
                                             int slot,
                                             int tid, int lid,
                                             int wm, int wn, int g, int t4) {
    const int t0    = mtile * 128;
    const int arow  = tid >> 2;
    const int aq    = tid & 3;
    const int atrow = t0 + arow;
    const bool trow_ok = (atrow < TRI);

    float acc[2][2][4];
    #pragma unroll
    for (int i = 0; i < 2; i++)
        #pragma unroll
        for (int j = 0; j < 2; j++)
            #pragma unroll
            for (int k = 0; k < 4; k++)
                acc[i][j][k] = 0.f;

    float4 aR[2][4];

    const int kmax = N_KTILES - 1;
    #define KCLAMP(i) (((kt0 + (i)) < kmax) ? (kt0 + (i)) : kmax)

    // ---- prologue: B0,B1 in flight; A0 in smem; aR holds kt0+1, kt0+2 ----
    cpasync_b(sb, 0, KCLAMP(0), tid);
    cp_commit();                                   // group for tile 0? (B0)
    cpasync_b(sb, 1, KCLAMP(1), tid);
    cp_commit();                                   // B1
    ldg_a(W, atrow, KCLAMP(0) * K_TILE, aq, trow_ok, aR[0]);
    sts_a(smem, 0, arow, aq, aR[0]);
    ldg_a(W, atrow, KCLAMP(1) * K_TILE, aq, trow_ok, aR[1]);
    ldg_a(W, atrow, KCLAMP(2) * K_TILE, aq, trow_ok, aR[0]);
    cp_wait<1>();                                  // B0 complete
    __syncthreads();

    for (int kt = 0; kt < n_kt; kt++) {
        const int sA_n = mod3(kt + 1);             // A stage for kt+1
        const int sB_n = mod3(kt + 2);             // B stage for kt+2

        cpasync_b(sb, sB_n, KCLAMP(kt + 2), tid);  // may be clamped dup
        cp_commit();                               // one group per iter
        if (kt + 1 < n_kt)
            sts_a(smem, sA_n, arow, aq, aR[(kt + 1) & 1]);
        if (kt + 3 < n_kt)
            ldg_a(W, atrow, (kt0 + kt + 3) * K_TILE, aq, trow_ok,
                  aR[(kt + 3) & 1]);

        compute_tile(sb, mod3(kt), mod3(kt), wm, wn, lid, acc);

        cp_wait<1>();                              // B(kt+1) complete
        __syncthreads();
    }
    cp_wait<0>();                                  // drain clamped prefetches
    #undef KCLAMP

    // ---- epilogue to slot ----
    float* vp = g_vp + (size_t)slot * BATCH * T_PAD;
    #pragma unroll
    for (int mt = 0; mt < 2; mt++) {
        #pragma unroll
        for (int nt = 0; nt < 2; nt++) {
            int r  = t0 + wm * 32 + mt * 16 + g;
            int cb = wn * 16 + nt * 8 + 2 * t4;
            vp[(size_t)cb       * T_PAD + r]     = acc[mt][nt][0];
            vp[(size_t)(cb + 1) * T_PAD + r]     = acc[mt][nt][1];
            vp[(size_t)cb       * T_PAD + r + 8] = acc[mt][nt][2];
            vp[(size_t)(cb + 1) * T_PAD + r + 8] = acc[mt][nt][3];
        }
    }
}

// ---------------------------------------------------------------------------
// Kernel 2: fp16 HMMA GEMM, 152 persistent CTAs x 512 threads (16 warps)
// Balanced flat (mtile, ktile) unit decomposition; <=2 segments per CTA.
// ---------------------------------------------------------------------------
__global__ __launch_bounds__(512, 1)
void gemm_tc_kernel(const float* __restrict__ W) {
    extern __shared__ char smem[];
    const uint32_t sb = smem_u32(smem);

    const int tid = threadIdx.x;
    const int wid = tid >> 5;
    const int lid = tid & 31;
    const int g   = lid >> 2;
    const int t4  = lid & 3;
    const int wm  = wid & 3;        // 4 row groups x 32
    const int wn  = wid >> 2;       // 4 col groups x 16

    const int cta   = blockIdx.x;
    int u     = start_u(cta);
    const int u_end = start_u(cta + 1);

    while (u < u_end) {
        const int m        = u / N_KTILES;
        const int tile_end = (m + 1) * N_KTILES;
        const int seg_end  = (u_end < tile_end) ? u_end : tile_end;
        const int kt0      = u - m * N_KTILES;
        const int n_kt     = seg_end - u;

        const int u0 = m * N_KTILES;
        int j0 = (int)(((long long)u0 * NCTA) / TOTAL_UNITS);
        while (start_u(j0 + 1) <= u0) j0++;
        while (start_u(j0) > u0) j0--;
        const int slot = cta - j0;

        gemm_segment(W, smem, sb, m, kt0, n_kt, slot,
                     tid, lid, wm, wn, g, t4);

        u = seg_end;
        if (u < u_end) __syncthreads();
    }
}

// ---------------------------------------------------------------------------
// Kernel 3: symmetric triu scatter + 4-slot reduce + bias
// ---------------------------------------------------------------------------
__global__ void scatter_kernel(float* __restrict__ out,
                               const float* __restrict__ bias) {
    int idx = blockIdx.x * blockDim.x + threadIdx.x;
    if (idx >= BATCH * NDIM * NDIM) return;
    int b = idx >> 14;
    int r = (idx >> 7) & 127;
    int c = idx & 127;
    int i = min(r, c);
    int j = max(r, c);
    int t = i * NDIM - (i * (i - 1)) / 2 + (j - i);
    float v = bias[t];
    #pragma unroll
    for (int s = 0; s < NSLOTS; s++)
        v += g_vp[((size_t)s * BATCH + b) * T_PAD + t];
    out[idx] = v;
}

// ---------------------------------------------------------------------------
extern "C" void kernel_launch(void* const* d_in, const int* in_sizes, int n_in,
                              void* d_out, int out_size) {
    const float* x       = (const float*)d_in[0];
    const float* conv1_w = (const float*)d_in[1];
    const float* conv1_b = (const float*)d_in[2];
    const float* conv2_w = (const float*)d_in[3];
    const float* conv2_b = (const float*)d_in[4];
    const float* out_w   = (const float*)d_in[5];
    const float* out_b   = (const float*)d_in[6];
    float* out = (float*)d_out;

    cudaFuncSetAttribute(gemm_tc_kernel,
                         cudaFuncAttributeMaxDynamicSharedMemorySize, SMEM_BYTES);

    conv_fuse_kernel<<<(BATCH * LIN_PAD) / 256, 256>>>(x, conv1_w, conv1_b,
                                                       conv2_w, conv2_b);
    gemm_tc_kernel<<<NCTA, 512, SMEM_BYTES>>>(out_w);
    scatter_kernel<<<(BATCH * NDIM * NDIM + 255) / 256, 256>>>(out, out_b);
}

// round 17
// speedup vs baseline: 1.8390x; 1.8390x over previous
#include <cuda_runtime.h>
#include <cuda_fp16.h>
#include <cstdint>

// ---------------------------------------------------------------------------
// Problem dims
// ---------------------------------------------------------------------------
#define HW        128
#define OW        126
#define LIN       15876              // (128-2)^2
#define K_TILE    64
#define N_KTILES  252                // LIN_PAD = 16128
#define LIN_PAD   (N_KTILES * K_TILE)
#define TRI       8256
#define BATCH     64
#define NDIM      128
#define T_PAD     8320               // 65*128
#define N_MTILES  65
#define NCTA      152                // GB300: 152 SMs, 1 CTA/SM
#define TOTAL_UNITS (N_MTILES * N_KTILES)   // 16380
#define NSLOTS    4

// SMEM layout, pitch 144 B (conflict-free ldmatrix).
// A stage: 128 x 144 = 18432 (fp16), x2;  B stage: 64 x 144 = 9216 (fp16), x3
#define A_PITCH   144
#define A_STG     18432u
#define A_OFF(s)  ((uint32_t)(s) * A_STG)
#define B_BASE    36864u
#define B_STG     9216u
#define B_OFF(st) (B_BASE + (uint32_t)(st) * B_STG)
#define SMEM_BYTES 64512

// ---------------------------------------------------------------------------
// Scratch (device globals — no allocation allowed)
// g_hb pad region [LIN, LIN_PAD) per batch is never written; device globals
// are zero-initialized at module load and stay zero -> deterministic.
// ---------------------------------------------------------------------------
__device__ __half g_hb[(size_t)BATCH * LIN_PAD];   // [b][l] fp16 h
__device__ float  g_vp[(size_t)NSLOTS * BATCH * T_PAD];

// ---------------------------------------------------------------------------
// helpers
// ---------------------------------------------------------------------------
__device__ __forceinline__ uint32_t smem_u32(const void* p) {
    uint32_t a;
    asm("{ .reg .u64 t; cvta.to.shared.u64 t, %1; cvt.u32.u64 %0, t; }"
        : "=r"(a) : "l"(p));
    return a;
}

__device__ __forceinline__ void cp_async16(uint32_t dst, const void* src) {
    asm volatile("cp.async.cg.shared.global [%0], [%1], 16;"
                 :: "r"(dst), "l"(src) : "memory");
}
__device__ __forceinline__ void cp_commit() {
    asm volatile("cp.async.commit_group;" ::: "memory");
}
template <int N>
__device__ __forceinline__ void cp_wait() {
    asm volatile("cp.async.wait_group %0;" :: "n"(N) : "memory");
}

__device__ __forceinline__ void ldsm4(uint32_t* r, uint32_t addr) {
    asm volatile("ldmatrix.sync.aligned.m8n8.x4.shared.b16 {%0,%1,%2,%3}, [%4];"
                 : "=r"(r[0]), "=r"(r[1]), "=r"(r[2]), "=r"(r[3]) : "r"(addr));
}

__device__ __forceinline__ void mma_f16(float* c,
                                        uint32_t a0, uint32_t a1, uint32_t a2, uint32_t a3,
                                        uint32_t b0, uint32_t b1) {
    asm volatile(
        "mma.sync.aligned.m16n8k16.row.col.f32.f16.f16.f32 "
        "{%0,%1,%2,%3}, {%4,%5,%6,%7}, {%8,%9}, {%0,%1,%2,%3};"
        : "+f"(c[0]), "+f"(c[1]), "+f"(c[2]), "+f"(c[3])
        : "r"(a0), "r"(a1), "r"(a2), "r"(a3), "r"(b0), "r"(b1));
}

__device__ __forceinline__ uint32_t pack_h2(float x, float y) {
    __half2 h = __floats2half2_rn(x, y);
    return *reinterpret_cast<uint32_t*>(&h);
}

// unit-space partition: CTA j owns units [start_u(j), start_u(j+1))
__device__ __forceinline__ int start_u(int j) {
    return (int)(((long long)j * TOTAL_UNITS) / NCTA);
}

// ---------------------------------------------------------------------------
// Kernel 1: fused conv -> fp16 h. 4 outputs per thread (3x6 input patch).
// 64 * 126 rows * 32 col-groups = 258048 threads = 1008 blocks x 256.
// ---------------------------------------------------------------------------
__global__ void conv_fuse_kernel(const float* __restrict__ x,
                                 const float* __restrict__ w1,
                                 const float* __restrict__ b1,
                                 const float* __restrict__ w2,
                                 const float* __restrict__ b2) {
    int idx = blockIdx.x * blockDim.x + threadIdx.x;
    int tj = idx & 31;                 // col group
    int i  = (idx >> 5) % OW;          // output row 0..125
    int b  = idx / (OW * 32);          // batch
    int j0 = tj * 4;                   // first output col (<= 124)

    const float* xp = x + (size_t)b * (HW * HW) + i * HW + j0;

    float in[3][6];
    #pragma unroll
    for (int r = 0; r < 3; r++)
        #pragma unroll
        for (int c = 0; c < 6; c++)
            in[r][c] = (j0 + c < HW) ? xp[r * HW + c] : 0.f;

    float o[4];
    #pragma unroll
    for (int jo = 0; jo < 4; jo++) {
        float acc = b2[0];
        #pragma unroll
        for (int cc = 0; cc < 4; cc++) {
            float s = b1[cc];
            #pragma unroll
            for (int di = 0; di < 3; di++)
                #pragma unroll
                for (int dj = 0; dj < 3; dj++)
                    s = fmaf(in[di][jo + dj], w1[cc * 9 + di * 3 + dj], s);
            acc = fmaf(w2[cc], fmaxf(s, 0.0f), acc);
        }
        o[jo] = acc;
    }

    // l = i*OW + j0 is even (OW even, j0 mult of 4) -> half2 stores aligned
    size_t l = (size_t)b * LIN_PAD + i * OW + j0;
    __half2* dst = reinterpret_cast<__half2*>(g_hb + l);
    dst[0] = __floats2half2_rn(o[0], o[1]);
    if (j0 + 3 < OW)                 // j0 == 124 -> only 2 valid outputs
        dst[1] = __floats2half2_rn(o[2], o[3]);
}

// ---------------------------------------------------------------------------
// GEMM helpers (512 threads: arow = tid>>2, aq = tid&3) — R15 verbatim
// ---------------------------------------------------------------------------
__device__ __forceinline__ void ldg_a(const float* __restrict__ W,
                                      int t, int l0, int aq, bool trow_ok,
                                      float4 (&a)[4]) {
    #pragma unroll
    for (int j = 0; j < 4; j++) {
        int l = l0 + (aq * 4 + j) * 4;
        if (trow_ok && l < LIN)
            a[j] = *reinterpret_cast<const float4*>(W + (size_t)t * LIN + l);
        else
            a[j] = make_float4(0.f, 0.f, 0.f, 0.f);
    }
}

__device__ __forceinline__ void sts_a(char* smem, int stage, int row, int aq,
                                      const float4 (&a)[4]) {
    uint32_t base = A_OFF(stage) + (uint32_t)row * A_PITCH + (uint32_t)aq * 32;
    *reinterpret_cast<uint4*>(smem + base) =
        make_uint4(pack_h2(a[0].x, a[0].y), pack_h2(a[0].z, a[0].w),
                   pack_h2(a[1].x, a[1].y), pack_h2(a[1].z, a[1].w));
    *reinterpret_cast<uint4*>(smem + base + 16) =
        make_uint4(pack_h2(a[2].x, a[2].y), pack_h2(a[2].z, a[2].w),
                   pack_h2(a[3].x, a[3].y), pack_h2(a[3].z, a[3].w));
}

// B tile: 64 rows x 128 B = 512 chunks, one cp.async per thread
__device__ __forceinline__ void cpasync_b(uint32_t sb, int st, int ktg, int tid) {
    int row = tid >> 3;
    int ch  = tid & 7;
    uint32_t dst = sb + B_OFF(st) + (uint32_t)row * A_PITCH + (uint32_t)ch * 16;
    cp_async16(dst, g_hb + (size_t)row * LIN_PAD + ktg * K_TILE + ch * 8);
}

// warp tile 32(m) x 16(n): 4 ksteps, fragment double-buffer (prefetch +1)
__device__ __forceinline__ void compute_tile(uint32_t sb, int stage, int bst,
                                             int wm, int wn, int lid,
                                             float (&acc)[2][2][4]) {
    const uint32_t lrow = (uint32_t)(lid & 15);
    const uint32_t lhi  = (uint32_t)((lid >> 4) << 4);

    uint32_t aH0 = sb + A_OFF(stage) + (wm * 32 + lrow) * A_PITCH + lhi;
    uint32_t aH1 = aH0 + 16 * A_PITCH;
    uint32_t bH  = sb + B_OFF(bst) + (wn * 16 + lrow) * A_PITCH + lhi;

    uint32_t a0[2][4], a1[2][4], bb[2][4];
    ldsm4(a0[0], aH0);
    ldsm4(a1[0], aH1);
    ldsm4(bb[0], bH);

    #pragma unroll
    for (int ks = 0; ks < 4; ks++) {
        const int cur = ks & 1;
        const int nxt = cur ^ 1;
        if (ks < 3) {
            const uint32_t ko = (uint32_t)(ks + 1) * 32;
            ldsm4(a0[nxt], aH0 + ko);
            ldsm4(a1[nxt], aH1 + ko);
            ldsm4(bb[nxt], bH + ko);
        }
        mma_f16(acc[0][0], a0[cur][0], a0[cur][1], a0[cur][2], a0[cur][3],
                bb[cur][0], bb[cur][2]);
        mma_f16(acc[0][1], a0[cur][0], a0[cur][1], a0[cur][2], a0[cur][3],
                bb[cur][1], bb[cur][3]);
        mma_f16(acc[1][0], a1[cur][0], a1[cur][1], a1[cur][2], a1[cur][3],
                bb[cur][0], bb[cur][2]);
        mma_f16(acc[1][1], a1[cur][0], a1[cur][1], a1[cur][2], a1[cur][3],
                bb[cur][1], bb[cur][3]);
    }
}

// one pipelined segment: M-tile `mtile`, K-tiles [kt0, kt0+n_kt), -> slot
__device__ __forceinline__ void gemm_segment(const float* __restrict__ W,
                                             char* smem, uint32_t sb,
                                             int mtile, int kt0, int n_kt,
                                             int slot,
                                             int tid, int wid, int lid,
                                             int wm, int wn, int g, int t4) {
    const int t0    = mtile * 128;
    const int arow  = tid >> 2;
    const int aq    = tid & 3;
    const int atrow = t0 + arow;
    const bool trow_ok = (atrow < TRI);

    float acc[2][2][4];
    #pragma unroll
    for (int i = 0; i < 2; i++)
        #pragma unroll
        for (int j = 0; j < 2; j++)
            #pragma unroll
            for (int k = 0; k < 4; k++)
                acc[i][j][k] = 0.f;

    float4 aR[4];

    // ---- prologue (guarded for n_kt == 1) ----
    cpasync_b(sb, 0, kt0 + 0, tid);
    cp_commit();
    if (n_kt > 1) cpasync_b(sb, 1, kt0 + 1, tid);
    cp_commit();
    ldg_a(W, atrow, (kt0 + 0) * K_TILE, aq, trow_ok, aR);
    sts_a(smem, 0, arow, aq, aR);
    if (n_kt > 1) ldg_a(W, atrow, (kt0 + 1) * K_TILE, aq, trow_ok, aR);
    cp_wait<1>();
    __syncthreads();

    int bs = 0;
    for (int kt = 0; kt < n_kt; kt++) {
        const int nxt_bs = (bs + 2 >= 3) ? bs - 1 : bs + 2;

        if (kt + 2 < n_kt) {
            cpasync_b(sb, nxt_bs, kt0 + kt + 2, tid);
            cp_commit();
        }
        if (kt + 1 < n_kt)
            sts_a(smem, (kt + 1) & 1, arow, aq, aR);
        if (kt + 2 < n_kt)
            ldg_a(W, atrow, (kt0 + kt + 2) * K_TILE, aq, trow_ok, aR);

        compute_tile(sb, kt & 1, bs, wm, wn, lid, acc);

        if (kt + 2 < n_kt)      cp_wait<1>();
        else if (kt + 1 < n_kt) cp_wait<0>();
        __syncthreads();

        bs = (bs + 1 >= 3) ? 0 : bs + 1;
    }

    // ---- epilogue to slot ----
    float* vp = g_vp + (size_t)slot * BATCH * T_PAD;
    #pragma unroll
    for (int mt = 0; mt < 2; mt++) {
        #pragma unroll
        for (int nt = 0; nt < 2; nt++) {
            int r  = t0 + wm * 32 + mt * 16 + g;
            int cb = wn * 16 + nt * 8 + 2 * t4;
            vp[(size_t)cb       * T_PAD + r]     = acc[mt][nt][0];
            vp[(size_t)(cb + 1) * T_PAD + r]     = acc[mt][nt][1];
            vp[(size_t)cb       * T_PAD + r + 8] = acc[mt][nt][2];
            vp[(size_t)(cb + 1) * T_PAD + r + 8] = acc[mt][nt][3];
        }
    }
}

// ---------------------------------------------------------------------------
// Kernel 2: fp16 HMMA GEMM, 152 persistent CTAs x 512 threads (16 warps)
// Balanced flat (mtile, ktile) unit decomposition; <=2 segments per CTA.
// ---------------------------------------------------------------------------
__global__ __launch_bounds__(512, 1)
void gemm_tc_kernel(const float* __restrict__ W) {
    extern __shared__ char smem[];
    const uint32_t sb = smem_u32(smem);

    const int tid = threadIdx.x;
    const int wid = tid >> 5;
    const int lid = tid & 31;
    const int g   = lid >> 2;
    const int t4  = lid & 3;
    const int wm  = wid & 3;        // 4 row groups x 32
    const int wn  = wid >> 2;       // 4 col groups x 16

    const int cta   = blockIdx.x;
    int u     = start_u(cta);
    const int u_end = start_u(cta + 1);

    while (u < u_end) {
        const int m        = u / N_KTILES;
        const int tile_end = (m + 1) * N_KTILES;
        const int seg_end  = (u_end < tile_end) ? u_end : tile_end;
        const int kt0      = u - m * N_KTILES;
        const int n_kt     = seg_end - u;

        // slot = cta - (first CTA whose range contains unit m*N_KTILES)
        const int u0 = m * N_KTILES;
        int j0 = (int)(((long long)u0 * NCTA) / TOTAL_UNITS);
        while (start_u(j0 + 1) <= u0) j0++;
        while (start_u(j0) > u0) j0--;
        const int slot = cta - j0;

        gemm_segment(W, smem, sb, m, kt0, n_kt, slot,
                     tid, wid, lid, wm, wn, g, t4);

        u = seg_end;
        if (u < u_end) __syncthreads();   // smem handoff between segments
    }
}

// ---------------------------------------------------------------------------
// Kernel 3: symmetric triu scatter + 4-slot reduce + bias
// ---------------------------------------------------------------------------
__global__ void scatter_kernel(float* __restrict__ out,
                               const float* __restrict__ bias) {
    int idx = blockIdx.x * blockDim.x + threadIdx.x;
    if (idx >= BATCH * NDIM * NDIM) return;
    int b = idx >> 14;
    int r = (idx >> 7) & 127;
    int c = idx & 127;
    int i = min(r, c);
    int j = max(r, c);
    int t = i * NDIM - (i * (i - 1)) / 2 + (j - i);
    float v = bias[t];
    #pragma unroll
    for (int s = 0; s < NSLOTS; s++)
        v += g_vp[((size_t)s * BATCH + b) * T_PAD + t];
    out[idx] = v;
}

// ---------------------------------------------------------------------------
extern "C" void kernel_launch(void* const* d_in, const int* in_sizes, int n_in,
                              void* d_out, int out_size) {
    const float* x       = (const float*)d_in[0];
    const float* conv1_w = (const float*)d_in[1];
    const float* conv1_b = (const float*)d_in[2];
    const float* conv2_w = (const float*)d_in[3];
    const float* conv2_b = (const float*)d_in[4];
    const float* out_w   = (const float*)d_in[5];
    const float* out_b   = (const float*)d_in[6];
    float* out = (float*)d_out;

    cudaFuncSetAttribute(gemm_tc_kernel,
                         cudaFuncAttributeMaxDynamicSharedMemorySize, SMEM_BYTES);

    conv_fuse_kernel<<<(BATCH * OW * 32) / 256, 256>>>(x, conv1_w, conv1_b,
                                                       conv2_w, conv2_b);
    gemm_tc_kernel<<<NCTA, 512, SMEM_BYTES>>>(out_w);
    scatter_kernel<<<(BATCH * NDIM * NDIM + 255) / 256, 256>>>(out, out_b);
}